// round 9
// baseline (speedup 1.0000x reference)
#include <cuda_runtime.h>
#include <cuda_fp16.h>
#include <cstdint>

// Problem constants
#define T_TOK 2048
#define H_DIM 1024
#define I_DIM 1408
#define E_NUM 8
#define K_TOP 2
#define CAP   1024

// ---------------- scratch (static __device__, no allocs) ----------------
__device__ __half g_xe [(size_t)E_NUM * CAP * H_DIM];        // 16 MB  fp16 gathered tokens
__device__ __half g_w1h[(size_t)E_NUM * 2 * I_DIM * H_DIM];  // 46 MB  fp16 w1
__device__ __half g_w2h[(size_t)E_NUM * H_DIM * I_DIM];      // 23 MB  fp16 w2
__device__ __half g_act[(size_t)E_NUM * CAP * I_DIM];        // 23 MB  fp16 silu(gate)*up
__device__ int    g_rowmap[E_NUM * CAP];
__device__ float  g_slotw [E_NUM * CAP];
__device__ int    g_counts[E_NUM];

// ---------------- routing: deterministic scan matching jnp.cumsum ----------------
__global__ void route_kernel(const int* __restrict__ ids, const float* __restrict__ wts) {
    __shared__ int sc[256][8];
    int t = threadIdx.x;
    int loc[8];
#pragma unroll
    for (int e = 0; e < 8; e++) loc[e] = 0;
    int base = t * 16;
#pragma unroll
    for (int j = 0; j < 16; j++) loc[ids[base + j]]++;
#pragma unroll
    for (int e = 0; e < 8; e++) sc[t][e] = loc[e];
    __syncthreads();
    for (int d = 1; d < 256; d <<= 1) {
        int v[8];
        if (t >= d) {
#pragma unroll
            for (int e = 0; e < 8; e++) v[e] = sc[t - d][e];
        }
        __syncthreads();
        if (t >= d) {
#pragma unroll
            for (int e = 0; e < 8; e++) sc[t][e] += v[e];
        }
        __syncthreads();
    }
    int pre[8];
#pragma unroll
    for (int e = 0; e < 8; e++) pre[e] = (t == 0) ? 0 : sc[t - 1][e];
    if (t == 0) {
#pragma unroll
        for (int e = 0; e < 8; e++) g_counts[e] = min(sc[255][e], CAP);
    }
    for (int j = 0; j < 16; j++) {
        int idx = base + j;
        int e = ids[idx];
        int p = pre[e]++;
        if (p < CAP) {
            g_rowmap[e * CAP + p] = idx >> 1;
            g_slotw [e * CAP + p] = wts[idx];
        }
    }
}

// ---------------- scatter hidden (fp32) -> x_e (fp16), zero pad rows ----------------
__global__ void scatter_kernel(const float* __restrict__ hidden) {
    int slot = blockIdx.x;
    int e = slot >> 10, p = slot & 1023;
    int cnt  = g_counts[e];
    int cpad = (cnt + 63) & ~63;           // 64-row GEMM tiles
    if (p >= cpad) return;
    __half2* dst = (__half2*)(g_xe + (size_t)slot * H_DIM);
    int t = threadIdx.x;
    if (p < cnt) {
        int token = g_rowmap[slot];
        const float4* src = (const float4*)(hidden + (size_t)token * H_DIM);
#pragma unroll
        for (int i = 0; i < 2; i++) {
            float4 v = src[t * 2 + i];
            dst[(t * 2 + i) * 2]     = __floats2half2_rn(v.x, v.y);
            dst[(t * 2 + i) * 2 + 1] = __floats2half2_rn(v.z, v.w);
        }
    } else {
        __half2 z = __floats2half2_rn(0.f, 0.f);
#pragma unroll
        for (int i = 0; i < 4; i++) dst[t * 4 + i] = z;
    }
}

// ---------------- weight convert fp32 -> fp16 (16B stores) ----------------
__global__ void convert_w_kernel(const float* __restrict__ w1, const float* __restrict__ w2) {
    const size_t N1 = (size_t)E_NUM * 2 * I_DIM * H_DIM / 8;   // units of 8 floats
    const size_t N2 = (size_t)E_NUM * H_DIM * I_DIM / 8;
    size_t stride = (size_t)gridDim.x * blockDim.x;
    for (size_t i = (size_t)blockIdx.x * blockDim.x + threadIdx.x; i < N1 + N2; i += stride) {
        const float4* src; uint4* dst; size_t k;
        if (i < N1) { src = (const float4*)w1; dst = (uint4*)g_w1h; k = i; }
        else        { src = (const float4*)w2; dst = (uint4*)g_w2h; k = i - N1; }
        float4 a = src[2 * k], b = src[2 * k + 1];
        __half2 h0 = __floats2half2_rn(a.x, a.y);
        __half2 h1 = __floats2half2_rn(a.z, a.w);
        __half2 h2 = __floats2half2_rn(b.x, b.y);
        __half2 h3 = __floats2half2_rn(b.z, b.w);
        uint4 o;
        o.x = *(unsigned*)&h0; o.y = *(unsigned*)&h1;
        o.z = *(unsigned*)&h2; o.w = *(unsigned*)&h3;
        dst[k] = o;
    }
}

// ---------------- GEMM helpers (mma.sync m16n8k16 fp16, fp32 accum) ----------------
__device__ __forceinline__ unsigned sptr(const void* p) {
    return (unsigned)__cvta_generic_to_shared(p);
}
__device__ __forceinline__ void cpasync16(unsigned s, const void* g) {
    asm volatile("cp.async.cg.shared.global [%0], [%1], 16;\n" :: "r"(s), "l"(g));
}
__device__ __forceinline__ void ldm4(unsigned s, unsigned& r0, unsigned& r1, unsigned& r2, unsigned& r3) {
    asm volatile("ldmatrix.sync.aligned.m8n8.x4.shared.b16 {%0,%1,%2,%3}, [%4];\n"
                 : "=r"(r0), "=r"(r1), "=r"(r2), "=r"(r3) : "r"(s));
}
__device__ __forceinline__ void mma16816(float* c, const unsigned* a, const unsigned* b) {
    asm volatile(
        "mma.sync.aligned.m16n8k16.row.col.f32.f16.f16.f32 "
        "{%0,%1,%2,%3},{%4,%5,%6,%7},{%8,%9},{%0,%1,%2,%3};\n"
        : "+f"(c[0]), "+f"(c[1]), "+f"(c[2]), "+f"(c[3])
        : "r"(a[0]), "r"(a[1]), "r"(a[2]), "r"(a[3]), "r"(b[0]), "r"(b[1]));
}
__device__ __forceinline__ float silu_f(float x) {
    return x / (1.f + __expf(-x));
}

#define LDS_H 40  // smem row stride (halves): 32 data + 8 pad -> conflict-free ldmatrix
#define STAGES 3
#define SA_STAGE (64 * LDS_H)                // A: 64 rows per stage
#define SB_STAGE (128 * LDS_H)               // B: 128 rows per stage
#define SMEM_GEMM (STAGES * (SA_STAGE + SB_STAGE) * 2)   // 46080 B -> 4 CTAs/SM

// waits until at most `rem` newest cp.async groups are still in flight
__device__ __forceinline__ void cp_wait_rem(int rem) {
    if (rem >= 1) asm volatile("cp.async.wait_group 1;\n" ::: "memory");
    else          asm volatile("cp.async.wait_group 0;\n" ::: "memory");
}

// ======================================================================
// GEMM core: 64x128 CTA tile, 4 warps of 32x64 (wm 0..1, wn 0..1),
// 128 threads, regs<=128, 3 stages -> 4 CTAs/SM (16 warps/SM).
// ======================================================================

// ---------------- GEMM1: x_e @ w1^T with fused SiLU*up epilogue -> act ----------------
// grid: (22 [64-wide n-tiles of I], 16 [64-row m-tiles of C], 8 [experts]); 128 threads
// D tile: 64 rows x (cols 0-63 = gate, 64-127 = up)
__global__ __launch_bounds__(128, 4) void gemm1_kernel() {
    int nblk = blockIdx.x, mblk = blockIdx.y, e = blockIdx.z;
    int cnt = g_counts[e];
    if (mblk * 64 >= cnt) return;

    extern __shared__ __align__(16) char smem_raw[];
    __half* sA = (__half*)smem_raw;                      // STAGES x SA_STAGE
    __half* sB = sA + STAGES * SA_STAGE;                 // STAGES x SB_STAGE

    int t = threadIdx.x;
    const __half* Ab = g_xe + (size_t)e * CAP * H_DIM + (size_t)mblk * 64 * H_DIM;
    const __half* W1 = g_w1h + (size_t)e * 2 * I_DIM * H_DIM;
    const int nb64 = nblk * 64;

    auto load_tile = [&](int kt, int buf) {
        int k0 = kt * 32;
#pragma unroll
        for (int i = 0; i < 2; i++) {            // A: 256 chunks (64 rows x 4)
            int q = t + i * 128;
            int row = q >> 2, ch = q & 3;
            cpasync16(sptr(sA + buf * SA_STAGE + row * LDS_H + ch * 8),
                      Ab + (size_t)row * H_DIM + k0 + ch * 8);
        }
#pragma unroll
        for (int i = 0; i < 4; i++) {            // B: 512 chunks (128 rows x 4)
            int q = t + i * 128;
            int row = q >> 2, ch = q & 3;
            int wrow = (row < 64) ? (nb64 + row) : (I_DIM + nb64 + row - 64);
            cpasync16(sptr(sB + buf * SB_STAGE + row * LDS_H + ch * 8),
                      W1 + (size_t)wrow * H_DIM + k0 + ch * 8);
        }
    };

    float acc[2][8][4];
#pragma unroll
    for (int a = 0; a < 2; a++)
#pragma unroll
        for (int b = 0; b < 8; b++)
#pragma unroll
            for (int c = 0; c < 4; c++) acc[a][b][c] = 0.f;

    int lane = t & 31, w = t >> 5, wm = w >> 1, wn = w & 1;
    int grp = lane >> 3, rr = lane & 7;
    int aro = rr + ((grp & 1) ? 8 : 0), aco = (grp & 2) ? 8 : 0;
    int bro = rr + ((grp & 2) ? 8 : 0), bco = (grp & 1) ? 8 : 0;

    const int KT = H_DIM / 32;  // 32
    load_tile(0, 0);
    asm volatile("cp.async.commit_group;\n" ::: "memory");
    load_tile(1, 1);
    asm volatile("cp.async.commit_group;\n" ::: "memory");
    for (int kt = 0; kt < KT; kt++) {
        cp_wait_rem(min(1, KT - 1 - kt));
        __syncthreads();
        if (kt + 2 < KT) {
            load_tile(kt + 2, (kt + 2) % STAGES);
            asm volatile("cp.async.commit_group;\n" ::: "memory");
        }
        int cur = kt % STAGES;
        const __half* a_base = sA + cur * SA_STAGE;
        const __half* b_base = sB + cur * SB_STAGE;
#pragma unroll
        for (int ks = 0; ks < 2; ks++) {
            int k0 = ks * 16;
            unsigned afr[2][4];
#pragma unroll
            for (int mf = 0; mf < 2; mf++)
                ldm4(sptr(a_base + (wm * 32 + mf * 16 + aro) * LDS_H + k0 + aco),
                     afr[mf][0], afr[mf][1], afr[mf][2], afr[mf][3]);
            unsigned bfr[8][2];
#pragma unroll
            for (int j2 = 0; j2 < 4; j2++) {
                unsigned r0, r1, r2, r3;
                ldm4(sptr(b_base + (wn * 64 + j2 * 16 + bro) * LDS_H + k0 + bco), r0, r1, r2, r3);
                bfr[j2 * 2][0] = r0; bfr[j2 * 2][1] = r1;
                bfr[j2 * 2 + 1][0] = r2; bfr[j2 * 2 + 1][1] = r3;
            }
#pragma unroll
            for (int mf = 0; mf < 2; mf++)
#pragma unroll
                for (int j = 0; j < 8; j++) mma16816(acc[mf][j], afr[mf], bfr[j]);
        }
        __syncthreads();
    }

    // ---- epilogue: gate warps (wn==0) publish to smem, up warps (wn==1) do silu*up ----
    float* gbuf = (float*)smem_raw;  // 64 x 64 fp32 = 16 KB (< 45 KB)
    if (wn == 0) {
#pragma unroll
        for (int mf = 0; mf < 2; mf++)
#pragma unroll
            for (int j = 0; j < 8; j++) {
                int r = wm * 32 + mf * 16 + (lane >> 2);
                int cc = j * 8 + (lane & 3) * 2;
                gbuf[r * 64 + cc]           = acc[mf][j][0];
                gbuf[r * 64 + cc + 1]       = acc[mf][j][1];
                gbuf[(r + 8) * 64 + cc]     = acc[mf][j][2];
                gbuf[(r + 8) * 64 + cc + 1] = acc[mf][j][3];
            }
    }
    __syncthreads();
    if (wn == 1) {
#pragma unroll
        for (int mf = 0; mf < 2; mf++)
#pragma unroll
            for (int j = 0; j < 8; j++) {
                int r = wm * 32 + mf * 16 + (lane >> 2);
                int cc = j * 8 + (lane & 3) * 2;
#pragma unroll
                for (int half_r = 0; half_r < 2; half_r++) {
                    int rr2 = r + half_r * 8;
                    float g0 = gbuf[rr2 * 64 + cc];
                    float g1 = gbuf[rr2 * 64 + cc + 1];
                    float u0 = acc[mf][j][half_r * 2 + 0];
                    float u1 = acc[mf][j][half_r * 2 + 1];
                    float v0 = silu_f(g0) * u0;
                    float v1 = silu_f(g1) * u1;
                    size_t row = (size_t)e * CAP + mblk * 64 + rr2;
                    *(__half2*)(g_act + row * I_DIM + nb64 + cc) = __floats2half2_rn(v0, v1);
                }
            }
    }
}

// ---------------- GEMM2: act @ w2^T with fused weighted scatter-add epilogue ----------------
// grid: (8 [128-wide n-tiles of H], 16 [64-row m-tiles of C], 8 [experts]); 128 threads
__global__ __launch_bounds__(128, 4) void gemm2_kernel(float* __restrict__ out) {
    int nblk = blockIdx.x, mblk = blockIdx.y, e = blockIdx.z;
    int cnt = g_counts[e];
    if (mblk * 64 >= cnt) return;

    extern __shared__ __align__(16) char smem_raw[];
    __half* sA = (__half*)smem_raw;
    __half* sB = sA + STAGES * SA_STAGE;

    int t = threadIdx.x;
    const __half* Ab = g_act + (size_t)e * CAP * I_DIM + (size_t)mblk * 64 * I_DIM;
    const __half* W2 = g_w2h + (size_t)e * H_DIM * I_DIM + (size_t)nblk * 128 * I_DIM;

    auto load_tile = [&](int kt, int buf) {
        int k0 = kt * 32;
#pragma unroll
        for (int i = 0; i < 2; i++) {
            int q = t + i * 128;
            int row = q >> 2, ch = q & 3;
            cpasync16(sptr(sA + buf * SA_STAGE + row * LDS_H + ch * 8),
                      Ab + (size_t)row * I_DIM + k0 + ch * 8);
        }
#pragma unroll
        for (int i = 0; i < 4; i++) {
            int q = t + i * 128;
            int row = q >> 2, ch = q & 3;
            cpasync16(sptr(sB + buf * SB_STAGE + row * LDS_H + ch * 8),
                      W2 + (size_t)row * I_DIM + k0 + ch * 8);
        }
    };

    float acc[2][8][4];
#pragma unroll
    for (int a = 0; a < 2; a++)
#pragma unroll
        for (int b = 0; b < 8; b++)
#pragma unroll
            for (int c = 0; c < 4; c++) acc[a][b][c] = 0.f;

    int lane = t & 31, w = t >> 5, wm = w >> 1, wn = w & 1;
    int grp = lane >> 3, rr = lane & 7;
    int aro = rr + ((grp & 1) ? 8 : 0), aco = (grp & 2) ? 8 : 0;
    int bro = rr + ((grp & 2) ? 8 : 0), bco = (grp & 1) ? 8 : 0;

    const int KT = I_DIM / 32;  // 44
    load_tile(0, 0);
    asm volatile("cp.async.commit_group;\n" ::: "memory");
    load_tile(1, 1);
    asm volatile("cp.async.commit_group;\n" ::: "memory");
    for (int kt = 0; kt < KT; kt++) {
        cp_wait_rem(min(1, KT - 1 - kt));
        __syncthreads();
        if (kt + 2 < KT) {
            load_tile(kt + 2, (kt + 2) % STAGES);
            asm volatile("cp.async.commit_group;\n" ::: "memory");
        }
        int cur = kt % STAGES;
        const __half* a_base = sA + cur * SA_STAGE;
        const __half* b_base = sB + cur * SB_STAGE;
#pragma unroll
        for (int ks = 0; ks < 2; ks++) {
            int k0 = ks * 16;
            unsigned afr[2][4];
#pragma unroll
            for (int mf = 0; mf < 2; mf++)
                ldm4(sptr(a_base + (wm * 32 + mf * 16 + aro) * LDS_H + k0 + aco),
                     afr[mf][0], afr[mf][1], afr[mf][2], afr[mf][3]);
            unsigned bfr[8][2];
#pragma unroll
            for (int j2 = 0; j2 < 4; j2++) {
                unsigned r0, r1, r2, r3;
                ldm4(sptr(b_base + (wn * 64 + j2 * 16 + bro) * LDS_H + k0 + bco), r0, r1, r2, r3);
                bfr[j2 * 2][0] = r0; bfr[j2 * 2][1] = r1;
                bfr[j2 * 2 + 1][0] = r2; bfr[j2 * 2 + 1][1] = r3;
            }
#pragma unroll
            for (int mf = 0; mf < 2; mf++)
#pragma unroll
                for (int j = 0; j < 8; j++) mma16816(acc[mf][j], afr[mf], bfr[j]);
        }
        __syncthreads();
    }

    // ---- epilogue: weighted scatter-add into out (red.global, no return) ----
#pragma unroll
    for (int mf = 0; mf < 2; mf++) {
        int r = wm * 32 + mf * 16 + (lane >> 2);
#pragma unroll
        for (int half_r = 0; half_r < 2; half_r++) {
            int slot = mblk * 64 + r + half_r * 8;
            if (slot < cnt) {
                int   token = g_rowmap[e * CAP + slot];
                float wgt   = g_slotw [e * CAP + slot];
                float* orow = out + (size_t)token * H_DIM;
#pragma unroll
                for (int j = 0; j < 8; j++) {
                    int col = nblk * 128 + wn * 64 + j * 8 + (lane & 3) * 2;
                    float v0 = wgt * acc[mf][j][half_r * 2 + 0];
                    float v1 = wgt * acc[mf][j][half_r * 2 + 1];
                    asm volatile("red.global.add.v2.f32 [%0], {%1, %2};\n"
                                 :: "l"(orow + col), "f"(v0), "f"(v1) : "memory");
                }
            }
        }
    }
}

// ---------------- launch ----------------
extern "C" void kernel_launch(void* const* d_in, const int* in_sizes, int n_in,
                              void* d_out, int out_size) {
    const float* hidden = (const float*)d_in[0];
    const float* w1     = (const float*)d_in[1];
    const float* w2     = (const float*)d_in[2];
    const float* tw     = (const float*)d_in[3];
    const int*   ids    = (const int*)d_in[4];
    float*       out    = (float*)d_out;

    cudaFuncSetAttribute(gemm1_kernel, cudaFuncAttributeMaxDynamicSharedMemorySize, SMEM_GEMM);
    cudaFuncSetAttribute(gemm2_kernel, cudaFuncAttributeMaxDynamicSharedMemorySize, SMEM_GEMM);

    cudaMemsetAsync(d_out, 0, (size_t)out_size * sizeof(float));
    route_kernel<<<1, 256>>>(ids, tw);
    convert_w_kernel<<<4096, 256>>>(w1, w2);
    scatter_kernel<<<E_NUM * CAP, 128>>>(hidden);
    gemm1_kernel<<<dim3(I_DIM / 64, CAP / 64, E_NUM), 128, SMEM_GEMM>>>();
    gemm2_kernel<<<dim3(H_DIM / 128, CAP / 64, E_NUM), 128, SMEM_GEMM>>>(out);
}

// round 10
// speedup vs baseline: 1.0064x; 1.0064x over previous
#include <cuda_runtime.h>
#include <cuda_fp16.h>
#include <cstdint>

// Problem constants
#define T_TOK 2048
#define H_DIM 1024
#define I_DIM 1408
#define E_NUM 8
#define K_TOP 2
#define CAP   1024

// ---------------- scratch (static __device__, no allocs) ----------------
__device__ __half g_xe [(size_t)E_NUM * CAP * H_DIM];        // 16 MB  fp16 gathered tokens
__device__ __half g_w1h[(size_t)E_NUM * 2 * I_DIM * H_DIM];  // 46 MB  fp16 w1
__device__ __half g_w2h[(size_t)E_NUM * H_DIM * I_DIM];      // 23 MB  fp16 w2
__device__ __half g_act[(size_t)E_NUM * CAP * I_DIM];        // 23 MB  fp16 silu(gate)*up
__device__ int    g_rowmap[E_NUM * CAP];
__device__ float  g_slotw [E_NUM * CAP];
__device__ int    g_counts[E_NUM];

// ---------------- routing: deterministic scan matching jnp.cumsum ----------------
__global__ void route_kernel(const int* __restrict__ ids, const float* __restrict__ wts) {
    __shared__ int sc[256][8];
    int t = threadIdx.x;
    int loc[8];
#pragma unroll
    for (int e = 0; e < 8; e++) loc[e] = 0;
    int base = t * 16;
#pragma unroll
    for (int j = 0; j < 16; j++) loc[ids[base + j]]++;
#pragma unroll
    for (int e = 0; e < 8; e++) sc[t][e] = loc[e];
    __syncthreads();
    for (int d = 1; d < 256; d <<= 1) {
        int v[8];
        if (t >= d) {
#pragma unroll
            for (int e = 0; e < 8; e++) v[e] = sc[t - d][e];
        }
        __syncthreads();
        if (t >= d) {
#pragma unroll
            for (int e = 0; e < 8; e++) sc[t][e] += v[e];
        }
        __syncthreads();
    }
    int pre[8];
#pragma unroll
    for (int e = 0; e < 8; e++) pre[e] = (t == 0) ? 0 : sc[t - 1][e];
    if (t == 0) {
#pragma unroll
        for (int e = 0; e < 8; e++) g_counts[e] = min(sc[255][e], CAP);
    }
    for (int j = 0; j < 16; j++) {
        int idx = base + j;
        int e = ids[idx];
        int p = pre[e]++;
        if (p < CAP) {
            g_rowmap[e * CAP + p] = idx >> 1;
            g_slotw [e * CAP + p] = wts[idx];
        }
    }
}

// ---------------- scatter hidden (fp32) -> x_e (fp16), zero pad rows ----------------
__global__ void scatter_kernel(const float* __restrict__ hidden) {
    int slot = blockIdx.x;
    int e = slot >> 10, p = slot & 1023;
    int cnt  = g_counts[e];
    int cpad = (cnt + 63) & ~63;           // 64-row GEMM tiles
    if (p >= cpad) return;
    __half2* dst = (__half2*)(g_xe + (size_t)slot * H_DIM);
    int t = threadIdx.x;
    if (p < cnt) {
        int token = g_rowmap[slot];
        const float4* src = (const float4*)(hidden + (size_t)token * H_DIM);
#pragma unroll
        for (int i = 0; i < 2; i++) {
            float4 v = src[t * 2 + i];
            dst[(t * 2 + i) * 2]     = __floats2half2_rn(v.x, v.y);
            dst[(t * 2 + i) * 2 + 1] = __floats2half2_rn(v.z, v.w);
        }
    } else {
        __half2 z = __floats2half2_rn(0.f, 0.f);
#pragma unroll
        for (int i = 0; i < 4; i++) dst[t * 4 + i] = z;
    }
}

// ---------------- weight convert fp32 -> fp16 (16B stores) ----------------
__global__ void convert_w_kernel(const float* __restrict__ w1, const float* __restrict__ w2) {
    const size_t N1 = (size_t)E_NUM * 2 * I_DIM * H_DIM / 8;   // units of 8 floats
    const size_t N2 = (size_t)E_NUM * H_DIM * I_DIM / 8;
    size_t stride = (size_t)gridDim.x * blockDim.x;
    for (size_t i = (size_t)blockIdx.x * blockDim.x + threadIdx.x; i < N1 + N2; i += stride) {
        const float4* src; uint4* dst; size_t k;
        if (i < N1) { src = (const float4*)w1; dst = (uint4*)g_w1h; k = i; }
        else        { src = (const float4*)w2; dst = (uint4*)g_w2h; k = i - N1; }
        float4 a = src[2 * k], b = src[2 * k + 1];
        __half2 h0 = __floats2half2_rn(a.x, a.y);
        __half2 h1 = __floats2half2_rn(a.z, a.w);
        __half2 h2 = __floats2half2_rn(b.x, b.y);
        __half2 h3 = __floats2half2_rn(b.z, b.w);
        uint4 o;
        o.x = *(unsigned*)&h0; o.y = *(unsigned*)&h1;
        o.z = *(unsigned*)&h2; o.w = *(unsigned*)&h3;
        dst[k] = o;
    }
}

// ---------------- GEMM helpers (mma.sync m16n8k16 fp16, fp32 accum) ----------------
__device__ __forceinline__ unsigned sptr(const void* p) {
    return (unsigned)__cvta_generic_to_shared(p);
}
__device__ __forceinline__ void cpasync16(unsigned s, const void* g) {
    asm volatile("cp.async.cg.shared.global [%0], [%1], 16;\n" :: "r"(s), "l"(g));
}
__device__ __forceinline__ void ldm4(unsigned s, unsigned& r0, unsigned& r1, unsigned& r2, unsigned& r3) {
    asm volatile("ldmatrix.sync.aligned.m8n8.x4.shared.b16 {%0,%1,%2,%3}, [%4];\n"
                 : "=r"(r0), "=r"(r1), "=r"(r2), "=r"(r3) : "r"(s));
}
__device__ __forceinline__ void mma16816(float* c, const unsigned* a, const unsigned* b) {
    asm volatile(
        "mma.sync.aligned.m16n8k16.row.col.f32.f16.f16.f32 "
        "{%0,%1,%2,%3},{%4,%5,%6,%7},{%8,%9},{%0,%1,%2,%3};\n"
        : "+f"(c[0]), "+f"(c[1]), "+f"(c[2]), "+f"(c[3])
        : "r"(a[0]), "r"(a[1]), "r"(a[2]), "r"(a[3]), "r"(b[0]), "r"(b[1]));
}
__device__ __forceinline__ float silu_f(float x) {
    return x / (1.f + __expf(-x));
}

#define LDS_H 40  // smem row stride (halves): 32 data + 8 pad -> conflict-free ldmatrix
#define STAGES 3
#define SA_STAGE (64 * LDS_H)                // A: 64 rows per stage
#define SB_STAGE (128 * LDS_H)               // B: 128 rows per stage
#define SMEM_GEMM (STAGES * (SA_STAGE + SB_STAGE) * 2)   // 46080 B -> 4 CTAs/SM

// waits until at most `rem` newest cp.async groups are still in flight
__device__ __forceinline__ void cp_wait_rem(int rem) {
    if (rem >= 1) asm volatile("cp.async.wait_group 1;\n" ::: "memory");
    else          asm volatile("cp.async.wait_group 0;\n" ::: "memory");
}

// ======================================================================
// GEMM core: 64x128 CTA tile, 4 warps of 32x64 (wm 0..1, wn 0..1),
// 128 threads, regs<=128, 3 stages -> 4 CTAs/SM (16 warps/SM).
// ======================================================================

// ---------------- GEMM1: x_e @ w1^T with fused SiLU*up epilogue -> act ----------------
// grid: (22 [64-wide n-tiles of I], 16 [64-row m-tiles of C], 8 [experts]); 128 threads
// D tile: 64 rows x (cols 0-63 = gate, 64-127 = up)
__global__ __launch_bounds__(128, 4) void gemm1_kernel() {
    int nblk = blockIdx.x, mblk = blockIdx.y, e = blockIdx.z;
    int cnt = g_counts[e];
    if (mblk * 64 >= cnt) return;

    extern __shared__ __align__(16) char smem_raw[];
    __half* sA = (__half*)smem_raw;                      // STAGES x SA_STAGE
    __half* sB = sA + STAGES * SA_STAGE;                 // STAGES x SB_STAGE

    int t = threadIdx.x;
    const __half* Ab = g_xe + (size_t)e * CAP * H_DIM + (size_t)mblk * 64 * H_DIM;
    const __half* W1 = g_w1h + (size_t)e * 2 * I_DIM * H_DIM;
    const int nb64 = nblk * 64;

    auto load_tile = [&](int kt, int buf) {
        int k0 = kt * 32;
#pragma unroll
        for (int i = 0; i < 2; i++) {            // A: 256 chunks (64 rows x 4)
            int q = t + i * 128;
            int row = q >> 2, ch = q & 3;
            cpasync16(sptr(sA + buf * SA_STAGE + row * LDS_H + ch * 8),
                      Ab + (size_t)row * H_DIM + k0 + ch * 8);
        }
#pragma unroll
        for (int i = 0; i < 4; i++) {            // B: 512 chunks (128 rows x 4)
            int q = t + i * 128;
            int row = q >> 2, ch = q & 3;
            int wrow = (row < 64) ? (nb64 + row) : (I_DIM + nb64 + row - 64);
            cpasync16(sptr(sB + buf * SB_STAGE + row * LDS_H + ch * 8),
                      W1 + (size_t)wrow * H_DIM + k0 + ch * 8);
        }
    };

    float acc[2][8][4];
#pragma unroll
    for (int a = 0; a < 2; a++)
#pragma unroll
        for (int b = 0; b < 8; b++)
#pragma unroll
            for (int c = 0; c < 4; c++) acc[a][b][c] = 0.f;

    int lane = t & 31, w = t >> 5, wm = w >> 1, wn = w & 1;
    int grp = lane >> 3, rr = lane & 7;
    int aro = rr + ((grp & 1) ? 8 : 0), aco = (grp & 2) ? 8 : 0;
    int bro = rr + ((grp & 2) ? 8 : 0), bco = (grp & 1) ? 8 : 0;

    const int KT = H_DIM / 32;  // 32
    load_tile(0, 0);
    asm volatile("cp.async.commit_group;\n" ::: "memory");
    load_tile(1, 1);
    asm volatile("cp.async.commit_group;\n" ::: "memory");
    for (int kt = 0; kt < KT; kt++) {
        cp_wait_rem(min(1, KT - 1 - kt));
        __syncthreads();
        if (kt + 2 < KT) {
            load_tile(kt + 2, (kt + 2) % STAGES);
            asm volatile("cp.async.commit_group;\n" ::: "memory");
        }
        int cur = kt % STAGES;
        const __half* a_base = sA + cur * SA_STAGE;
        const __half* b_base = sB + cur * SB_STAGE;
#pragma unroll
        for (int ks = 0; ks < 2; ks++) {
            int k0 = ks * 16;
            unsigned afr[2][4];
#pragma unroll
            for (int mf = 0; mf < 2; mf++)
                ldm4(sptr(a_base + (wm * 32 + mf * 16 + aro) * LDS_H + k0 + aco),
                     afr[mf][0], afr[mf][1], afr[mf][2], afr[mf][3]);
            unsigned bfr[8][2];
#pragma unroll
            for (int j2 = 0; j2 < 4; j2++) {
                unsigned r0, r1, r2, r3;
                ldm4(sptr(b_base + (wn * 64 + j2 * 16 + bro) * LDS_H + k0 + bco), r0, r1, r2, r3);
                bfr[j2 * 2][0] = r0; bfr[j2 * 2][1] = r1;
                bfr[j2 * 2 + 1][0] = r2; bfr[j2 * 2 + 1][1] = r3;
            }
#pragma unroll
            for (int mf = 0; mf < 2; mf++)
#pragma unroll
                for (int j = 0; j < 8; j++) mma16816(acc[mf][j], afr[mf], bfr[j]);
        }
        __syncthreads();
    }

    // ---- epilogue: gate warps (wn==0) publish to smem, up warps (wn==1) do silu*up ----
    float* gbuf = (float*)smem_raw;  // 64 x 64 fp32 = 16 KB (< 45 KB)
    if (wn == 0) {
#pragma unroll
        for (int mf = 0; mf < 2; mf++)
#pragma unroll
            for (int j = 0; j < 8; j++) {
                int r = wm * 32 + mf * 16 + (lane >> 2);
                int cc = j * 8 + (lane & 3) * 2;
                gbuf[r * 64 + cc]           = acc[mf][j][0];
                gbuf[r * 64 + cc + 1]       = acc[mf][j][1];
                gbuf[(r + 8) * 64 + cc]     = acc[mf][j][2];
                gbuf[(r + 8) * 64 + cc + 1] = acc[mf][j][3];
            }
    }
    __syncthreads();
    if (wn == 1) {
#pragma unroll
        for (int mf = 0; mf < 2; mf++)
#pragma unroll
            for (int j = 0; j < 8; j++) {
                int r = wm * 32 + mf * 16 + (lane >> 2);
                int cc = j * 8 + (lane & 3) * 2;
#pragma unroll
                for (int half_r = 0; half_r < 2; half_r++) {
                    int rr2 = r + half_r * 8;
                    float g0 = gbuf[rr2 * 64 + cc];
                    float g1 = gbuf[rr2 * 64 + cc + 1];
                    float u0 = acc[mf][j][half_r * 2 + 0];
                    float u1 = acc[mf][j][half_r * 2 + 1];
                    float v0 = silu_f(g0) * u0;
                    float v1 = silu_f(g1) * u1;
                    size_t row = (size_t)e * CAP + mblk * 64 + rr2;
                    *(__half2*)(g_act + row * I_DIM + nb64 + cc) = __floats2half2_rn(v0, v1);
                }
            }
    }
}

// ---------------- GEMM2: act @ w2^T with fused weighted scatter-add epilogue ----------------
// grid: (8 [128-wide n-tiles of H], 16 [64-row m-tiles of C], 8 [experts]); 128 threads
__global__ __launch_bounds__(128, 4) void gemm2_kernel(float* __restrict__ out) {
    int nblk = blockIdx.x, mblk = blockIdx.y, e = blockIdx.z;
    int cnt = g_counts[e];
    if (mblk * 64 >= cnt) return;

    extern __shared__ __align__(16) char smem_raw[];
    __half* sA = (__half*)smem_raw;
    __half* sB = sA + STAGES * SA_STAGE;

    int t = threadIdx.x;
    const __half* Ab = g_act + (size_t)e * CAP * I_DIM + (size_t)mblk * 64 * I_DIM;
    const __half* W2 = g_w2h + (size_t)e * H_DIM * I_DIM + (size_t)nblk * 128 * I_DIM;

    auto load_tile = [&](int kt, int buf) {
        int k0 = kt * 32;
#pragma unroll
        for (int i = 0; i < 2; i++) {
            int q = t + i * 128;
            int row = q >> 2, ch = q & 3;
            cpasync16(sptr(sA + buf * SA_STAGE + row * LDS_H + ch * 8),
                      Ab + (size_t)row * I_DIM + k0 + ch * 8);
        }
#pragma unroll
        for (int i = 0; i < 4; i++) {
            int q = t + i * 128;
            int row = q >> 2, ch = q & 3;
            cpasync16(sptr(sB + buf * SB_STAGE + row * LDS_H + ch * 8),
                      W2 + (size_t)row * I_DIM + k0 + ch * 8);
        }
    };

    float acc[2][8][4];
#pragma unroll
    for (int a = 0; a < 2; a++)
#pragma unroll
        for (int b = 0; b < 8; b++)
#pragma unroll
            for (int c = 0; c < 4; c++) acc[a][b][c] = 0.f;

    int lane = t & 31, w = t >> 5, wm = w >> 1, wn = w & 1;
    int grp = lane >> 3, rr = lane & 7;
    int aro = rr + ((grp & 1) ? 8 : 0), aco = (grp & 2) ? 8 : 0;
    int bro = rr + ((grp & 2) ? 8 : 0), bco = (grp & 1) ? 8 : 0;

    const int KT = I_DIM / 32;  // 44
    load_tile(0, 0);
    asm volatile("cp.async.commit_group;\n" ::: "memory");
    load_tile(1, 1);
    asm volatile("cp.async.commit_group;\n" ::: "memory");
    for (int kt = 0; kt < KT; kt++) {
        cp_wait_rem(min(1, KT - 1 - kt));
        __syncthreads();
        if (kt + 2 < KT) {
            load_tile(kt + 2, (kt + 2) % STAGES);
            asm volatile("cp.async.commit_group;\n" ::: "memory");
        }
        int cur = kt % STAGES;
        const __half* a_base = sA + cur * SA_STAGE;
        const __half* b_base = sB + cur * SB_STAGE;
#pragma unroll
        for (int ks = 0; ks < 2; ks++) {
            int k0 = ks * 16;
            unsigned afr[2][4];
#pragma unroll
            for (int mf = 0; mf < 2; mf++)
                ldm4(sptr(a_base + (wm * 32 + mf * 16 + aro) * LDS_H + k0 + aco),
                     afr[mf][0], afr[mf][1], afr[mf][2], afr[mf][3]);
            unsigned bfr[8][2];
#pragma unroll
            for (int j2 = 0; j2 < 4; j2++) {
                unsigned r0, r1, r2, r3;
                ldm4(sptr(b_base + (wn * 64 + j2 * 16 + bro) * LDS_H + k0 + bco), r0, r1, r2, r3);
                bfr[j2 * 2][0] = r0; bfr[j2 * 2][1] = r1;
                bfr[j2 * 2 + 1][0] = r2; bfr[j2 * 2 + 1][1] = r3;
            }
#pragma unroll
            for (int mf = 0; mf < 2; mf++)
#pragma unroll
                for (int j = 0; j < 8; j++) mma16816(acc[mf][j], afr[mf], bfr[j]);
        }
        __syncthreads();
    }

    // ---- epilogue: weighted scatter-add into out (red.global, no return) ----
#pragma unroll
    for (int mf = 0; mf < 2; mf++) {
        int r = wm * 32 + mf * 16 + (lane >> 2);
#pragma unroll
        for (int half_r = 0; half_r < 2; half_r++) {
            int slot = mblk * 64 + r + half_r * 8;
            if (slot < cnt) {
                int   token = g_rowmap[e * CAP + slot];
                float wgt   = g_slotw [e * CAP + slot];
                float* orow = out + (size_t)token * H_DIM;
#pragma unroll
                for (int j = 0; j < 8; j++) {
                    int col = nblk * 128 + wn * 64 + j * 8 + (lane & 3) * 2;
                    float v0 = wgt * acc[mf][j][half_r * 2 + 0];
                    float v1 = wgt * acc[mf][j][half_r * 2 + 1];
                    asm volatile("red.global.add.v2.f32 [%0], {%1, %2};\n"
                                 :: "l"(orow + col), "f"(v0), "f"(v1) : "memory");
                }
            }
        }
    }
}

// ---------------- launch ----------------
extern "C" void kernel_launch(void* const* d_in, const int* in_sizes, int n_in,
                              void* d_out, int out_size) {
    const float* hidden = (const float*)d_in[0];
    const float* w1     = (const float*)d_in[1];
    const float* w2     = (const float*)d_in[2];
    const float* tw     = (const float*)d_in[3];
    const int*   ids    = (const int*)d_in[4];
    float*       out    = (float*)d_out;

    cudaFuncSetAttribute(gemm1_kernel, cudaFuncAttributeMaxDynamicSharedMemorySize, SMEM_GEMM);
    cudaFuncSetAttribute(gemm2_kernel, cudaFuncAttributeMaxDynamicSharedMemorySize, SMEM_GEMM);

    cudaMemsetAsync(d_out, 0, (size_t)out_size * sizeof(float));
    route_kernel<<<1, 256>>>(ids, tw);
    convert_w_kernel<<<4096, 256>>>(w1, w2);
    scatter_kernel<<<E_NUM * CAP, 128>>>(hidden);
    gemm1_kernel<<<dim3(I_DIM / 64, CAP / 64, E_NUM), 128, SMEM_GEMM>>>();
    gemm2_kernel<<<dim3(H_DIM / 128, CAP / 64, E_NUM), 128, SMEM_GEMM>>>(out);
}

// round 11
// speedup vs baseline: 1.0560x; 1.0493x over previous
#include <cuda_runtime.h>
#include <cuda_fp16.h>
#include <cstdint>

// Problem constants
#define T_TOK 2048
#define H_DIM 1024
#define I_DIM 1408
#define E_NUM 8
#define K_TOP 2
#define CAP   1024

// ---------------- scratch (static __device__, no allocs) ----------------
__device__ __half g_xe [(size_t)E_NUM * CAP * H_DIM];        // 16 MB  fp16 gathered tokens
__device__ __half g_w1h[(size_t)E_NUM * 2 * I_DIM * H_DIM];  // 46 MB  fp16 w1
__device__ __half g_w2h[(size_t)E_NUM * H_DIM * I_DIM];      // 23 MB  fp16 w2
__device__ __half g_act[(size_t)E_NUM * CAP * I_DIM];        // 23 MB  fp16 silu(gate)*up
__device__ int    g_rowmap[E_NUM * CAP];
__device__ float  g_slotw [E_NUM * CAP];
__device__ int    g_counts[E_NUM];

// ---------------- routing: deterministic scan matching jnp.cumsum ----------------
__global__ void route_kernel(const int* __restrict__ ids, const float* __restrict__ wts) {
    __shared__ int sc[256][8];
    int t = threadIdx.x;
    int loc[8];
#pragma unroll
    for (int e = 0; e < 8; e++) loc[e] = 0;
    int base = t * 16;
#pragma unroll
    for (int j = 0; j < 16; j++) loc[ids[base + j]]++;
#pragma unroll
    for (int e = 0; e < 8; e++) sc[t][e] = loc[e];
    __syncthreads();
    for (int d = 1; d < 256; d <<= 1) {
        int v[8];
        if (t >= d) {
#pragma unroll
            for (int e = 0; e < 8; e++) v[e] = sc[t - d][e];
        }
        __syncthreads();
        if (t >= d) {
#pragma unroll
            for (int e = 0; e < 8; e++) sc[t][e] += v[e];
        }
        __syncthreads();
    }
    int pre[8];
#pragma unroll
    for (int e = 0; e < 8; e++) pre[e] = (t == 0) ? 0 : sc[t - 1][e];
    if (t == 0) {
#pragma unroll
        for (int e = 0; e < 8; e++) g_counts[e] = min(sc[255][e], CAP);
    }
    for (int j = 0; j < 16; j++) {
        int idx = base + j;
        int e = ids[idx];
        int p = pre[e]++;
        if (p < CAP) {
            g_rowmap[e * CAP + p] = idx >> 1;
            g_slotw [e * CAP + p] = wts[idx];
        }
    }
}

// ---------------- scatter hidden (fp32) -> x_e (fp16), zero pad rows ----------------
__global__ void scatter_kernel(const float* __restrict__ hidden) {
    int slot = blockIdx.x;
    int e = slot >> 10, p = slot & 1023;
    int cnt  = g_counts[e];
    int cpad = (cnt + 63) & ~63;           // 64-row GEMM tiles
    if (p >= cpad) return;
    __half2* dst = (__half2*)(g_xe + (size_t)slot * H_DIM);
    int t = threadIdx.x;
    if (p < cnt) {
        int token = g_rowmap[slot];
        const float4* src = (const float4*)(hidden + (size_t)token * H_DIM);
#pragma unroll
        for (int i = 0; i < 2; i++) {
            float4 v = src[t * 2 + i];
            dst[(t * 2 + i) * 2]     = __floats2half2_rn(v.x, v.y);
            dst[(t * 2 + i) * 2 + 1] = __floats2half2_rn(v.z, v.w);
        }
    } else {
        __half2 z = __floats2half2_rn(0.f, 0.f);
#pragma unroll
        for (int i = 0; i < 4; i++) dst[t * 4 + i] = z;
    }
}

// ---------------- weight converts fp32 -> fp16 (exact grid, 16B stores) ----------------
__device__ __forceinline__ uint4 pack8(float4 a, float4 b) {
    __half2 h0 = __floats2half2_rn(a.x, a.y);
    __half2 h1 = __floats2half2_rn(a.z, a.w);
    __half2 h2 = __floats2half2_rn(b.x, b.y);
    __half2 h3 = __floats2half2_rn(b.z, b.w);
    uint4 o;
    o.x = *(unsigned*)&h0; o.y = *(unsigned*)&h1;
    o.z = *(unsigned*)&h2; o.w = *(unsigned*)&h3;
    return o;
}
__global__ void convert_w1_kernel(const float* __restrict__ w1) {
    size_t i = (size_t)blockIdx.x * blockDim.x + threadIdx.x;   // < E*2I*H/8
    const float4* src = (const float4*)w1;
    ((uint4*)g_w1h)[i] = pack8(src[2 * i], src[2 * i + 1]);
}
__global__ void convert_w2_kernel(const float* __restrict__ w2) {
    size_t i = (size_t)blockIdx.x * blockDim.x + threadIdx.x;   // < E*H*I/8
    const float4* src = (const float4*)w2;
    ((uint4*)g_w2h)[i] = pack8(src[2 * i], src[2 * i + 1]);
}

// ---------------- GEMM helpers (mma.sync m16n8k16 fp16, fp32 accum) ----------------
__device__ __forceinline__ unsigned sptr(const void* p) {
    return (unsigned)__cvta_generic_to_shared(p);
}
__device__ __forceinline__ void cpasync16(unsigned s, const void* g) {
    asm volatile("cp.async.cg.shared.global [%0], [%1], 16;\n" :: "r"(s), "l"(g));
}
__device__ __forceinline__ void ldm4(unsigned s, unsigned& r0, unsigned& r1, unsigned& r2, unsigned& r3) {
    asm volatile("ldmatrix.sync.aligned.m8n8.x4.shared.b16 {%0,%1,%2,%3}, [%4];\n"
                 : "=r"(r0), "=r"(r1), "=r"(r2), "=r"(r3) : "r"(s));
}
__device__ __forceinline__ void mma16816(float* c, const unsigned* a, const unsigned* b) {
    asm volatile(
        "mma.sync.aligned.m16n8k16.row.col.f32.f16.f16.f32 "
        "{%0,%1,%2,%3},{%4,%5,%6,%7},{%8,%9},{%0,%1,%2,%3};\n"
        : "+f"(c[0]), "+f"(c[1]), "+f"(c[2]), "+f"(c[3])
        : "r"(a[0]), "r"(a[1]), "r"(a[2]), "r"(a[3]), "r"(b[0]), "r"(b[1]));
}
__device__ __forceinline__ float silu_f(float x) {
    return x / (1.f + __expf(-x));
}

#define LDS_H 40  // smem row stride (halves): 32 data + 8 pad -> conflict-free ldmatrix
#define STAGES 3
#define SA_STAGE (64 * LDS_H)                // A: 64 rows per stage
#define SB_STAGE (128 * LDS_H)               // B: 128 rows per stage
#define SMEM_GEMM (STAGES * (SA_STAGE + SB_STAGE) * 2)   // 46080 B -> 4 CTAs/SM

// waits until at most `rem` newest cp.async groups are still in flight
__device__ __forceinline__ void cp_wait_rem(int rem) {
    if (rem >= 1) asm volatile("cp.async.wait_group 1;\n" ::: "memory");
    else          asm volatile("cp.async.wait_group 0;\n" ::: "memory");
}

// ======================================================================
// GEMM core: 64x128 CTA tile, 4 warps of 32x64, 128 threads, regs<=128,
// 3 stages -> 4 CTAs/SM. ONE barrier per k-iteration (the top barrier
// guarantees iter kt-1's smem reads finished before the kt+2 load
// overwrites that ring slot).
// ======================================================================

// ---------------- GEMM1: x_e @ w1^T with fused SiLU*up epilogue -> act ----------------
__global__ __launch_bounds__(128, 4) void gemm1_kernel() {
    int nblk = blockIdx.x, mblk = blockIdx.y, e = blockIdx.z;
    int cnt = g_counts[e];
    if (mblk * 64 >= cnt) return;

    extern __shared__ __align__(16) char smem_raw[];
    __half* sA = (__half*)smem_raw;                      // STAGES x SA_STAGE
    __half* sB = sA + STAGES * SA_STAGE;                 // STAGES x SB_STAGE

    int t = threadIdx.x;
    const __half* Ab = g_xe + (size_t)e * CAP * H_DIM + (size_t)mblk * 64 * H_DIM;
    const __half* W1 = g_w1h + (size_t)e * 2 * I_DIM * H_DIM;
    const int nb64 = nblk * 64;

    auto load_tile = [&](int kt, int buf) {
        int k0 = kt * 32;
#pragma unroll
        for (int i = 0; i < 2; i++) {            // A: 256 chunks (64 rows x 4)
            int q = t + i * 128;
            int row = q >> 2, ch = q & 3;
            cpasync16(sptr(sA + buf * SA_STAGE + row * LDS_H + ch * 8),
                      Ab + (size_t)row * H_DIM + k0 + ch * 8);
        }
#pragma unroll
        for (int i = 0; i < 4; i++) {            // B: 512 chunks (128 rows x 4)
            int q = t + i * 128;
            int row = q >> 2, ch = q & 3;
            int wrow = (row < 64) ? (nb64 + row) : (I_DIM + nb64 + row - 64);
            cpasync16(sptr(sB + buf * SB_STAGE + row * LDS_H + ch * 8),
                      W1 + (size_t)wrow * H_DIM + k0 + ch * 8);
        }
    };

    float acc[2][8][4];
#pragma unroll
    for (int a = 0; a < 2; a++)
#pragma unroll
        for (int b = 0; b < 8; b++)
#pragma unroll
            for (int c = 0; c < 4; c++) acc[a][b][c] = 0.f;

    int lane = t & 31, w = t >> 5, wm = w >> 1, wn = w & 1;
    int grp = lane >> 3, rr = lane & 7;
    int aro = rr + ((grp & 1) ? 8 : 0), aco = (grp & 2) ? 8 : 0;
    int bro = rr + ((grp & 2) ? 8 : 0), bco = (grp & 1) ? 8 : 0;

    const int KT = H_DIM / 32;  // 32
    load_tile(0, 0);
    asm volatile("cp.async.commit_group;\n" ::: "memory");
    load_tile(1, 1);
    asm volatile("cp.async.commit_group;\n" ::: "memory");
    for (int kt = 0; kt < KT; kt++) {
        cp_wait_rem(min(1, KT - 1 - kt));
        __syncthreads();
        if (kt + 2 < KT) {
            load_tile(kt + 2, (kt + 2) % STAGES);
            asm volatile("cp.async.commit_group;\n" ::: "memory");
        }
        int cur = kt % STAGES;
        const __half* a_base = sA + cur * SA_STAGE;
        const __half* b_base = sB + cur * SB_STAGE;
#pragma unroll
        for (int ks = 0; ks < 2; ks++) {
            int k0 = ks * 16;
            unsigned afr[2][4];
#pragma unroll
            for (int mf = 0; mf < 2; mf++)
                ldm4(sptr(a_base + (wm * 32 + mf * 16 + aro) * LDS_H + k0 + aco),
                     afr[mf][0], afr[mf][1], afr[mf][2], afr[mf][3]);
            unsigned bfr[8][2];
#pragma unroll
            for (int j2 = 0; j2 < 4; j2++) {
                unsigned r0, r1, r2, r3;
                ldm4(sptr(b_base + (wn * 64 + j2 * 16 + bro) * LDS_H + k0 + bco), r0, r1, r2, r3);
                bfr[j2 * 2][0] = r0; bfr[j2 * 2][1] = r1;
                bfr[j2 * 2 + 1][0] = r2; bfr[j2 * 2 + 1][1] = r3;
            }
#pragma unroll
            for (int mf = 0; mf < 2; mf++)
#pragma unroll
                for (int j = 0; j < 8; j++) mma16816(acc[mf][j], afr[mf], bfr[j]);
        }
    }
    __syncthreads();   // all warps done with smem tiles before gbuf reuse

    // ---- epilogue: gate warps (wn==0) publish to smem, up warps (wn==1) do silu*up ----
    float* gbuf = (float*)smem_raw;  // 64 x 64 fp32 = 16 KB (< 45 KB)
    if (wn == 0) {
#pragma unroll
        for (int mf = 0; mf < 2; mf++)
#pragma unroll
            for (int j = 0; j < 8; j++) {
                int r = wm * 32 + mf * 16 + (lane >> 2);
                int cc = j * 8 + (lane & 3) * 2;
                gbuf[r * 64 + cc]           = acc[mf][j][0];
                gbuf[r * 64 + cc + 1]       = acc[mf][j][1];
                gbuf[(r + 8) * 64 + cc]     = acc[mf][j][2];
                gbuf[(r + 8) * 64 + cc + 1] = acc[mf][j][3];
            }
    }
    __syncthreads();
    if (wn == 1) {
#pragma unroll
        for (int mf = 0; mf < 2; mf++)
#pragma unroll
            for (int j = 0; j < 8; j++) {
                int r = wm * 32 + mf * 16 + (lane >> 2);
                int cc = j * 8 + (lane & 3) * 2;
#pragma unroll
                for (int half_r = 0; half_r < 2; half_r++) {
                    int rr2 = r + half_r * 8;
                    float g0 = gbuf[rr2 * 64 + cc];
                    float g1 = gbuf[rr2 * 64 + cc + 1];
                    float u0 = acc[mf][j][half_r * 2 + 0];
                    float u1 = acc[mf][j][half_r * 2 + 1];
                    float v0 = silu_f(g0) * u0;
                    float v1 = silu_f(g1) * u1;
                    size_t row = (size_t)e * CAP + mblk * 64 + rr2;
                    *(__half2*)(g_act + row * I_DIM + nb64 + cc) = __floats2half2_rn(v0, v1);
                }
            }
    }
}

// ---------------- GEMM2: act @ w2^T with fused weighted scatter-add epilogue ----------------
__global__ __launch_bounds__(128, 4) void gemm2_kernel(float* __restrict__ out) {
    int nblk = blockIdx.x, mblk = blockIdx.y, e = blockIdx.z;
    int cnt = g_counts[e];
    if (mblk * 64 >= cnt) return;

    extern __shared__ __align__(16) char smem_raw[];
    __half* sA = (__half*)smem_raw;
    __half* sB = sA + STAGES * SA_STAGE;

    int t = threadIdx.x;
    const __half* Ab = g_act + (size_t)e * CAP * I_DIM + (size_t)mblk * 64 * I_DIM;
    const __half* W2 = g_w2h + (size_t)e * H_DIM * I_DIM + (size_t)nblk * 128 * I_DIM;

    auto load_tile = [&](int kt, int buf) {
        int k0 = kt * 32;
#pragma unroll
        for (int i = 0; i < 2; i++) {
            int q = t + i * 128;
            int row = q >> 2, ch = q & 3;
            cpasync16(sptr(sA + buf * SA_STAGE + row * LDS_H + ch * 8),
                      Ab + (size_t)row * I_DIM + k0 + ch * 8);
        }
#pragma unroll
        for (int i = 0; i < 4; i++) {
            int q = t + i * 128;
            int row = q >> 2, ch = q & 3;
            cpasync16(sptr(sB + buf * SB_STAGE + row * LDS_H + ch * 8),
                      W2 + (size_t)row * I_DIM + k0 + ch * 8);
        }
    };

    float acc[2][8][4];
#pragma unroll
    for (int a = 0; a < 2; a++)
#pragma unroll
        for (int b = 0; b < 8; b++)
#pragma unroll
            for (int c = 0; c < 4; c++) acc[a][b][c] = 0.f;

    int lane = t & 31, w = t >> 5, wm = w >> 1, wn = w & 1;
    int grp = lane >> 3, rr = lane & 7;
    int aro = rr + ((grp & 1) ? 8 : 0), aco = (grp & 2) ? 8 : 0;
    int bro = rr + ((grp & 2) ? 8 : 0), bco = (grp & 1) ? 8 : 0;

    const int KT = I_DIM / 32;  // 44
    load_tile(0, 0);
    asm volatile("cp.async.commit_group;\n" ::: "memory");
    load_tile(1, 1);
    asm volatile("cp.async.commit_group;\n" ::: "memory");
    for (int kt = 0; kt < KT; kt++) {
        cp_wait_rem(min(1, KT - 1 - kt));
        __syncthreads();
        if (kt + 2 < KT) {
            load_tile(kt + 2, (kt + 2) % STAGES);
            asm volatile("cp.async.commit_group;\n" ::: "memory");
        }
        int cur = kt % STAGES;
        const __half* a_base = sA + cur * SA_STAGE;
        const __half* b_base = sB + cur * SB_STAGE;
#pragma unroll
        for (int ks = 0; ks < 2; ks++) {
            int k0 = ks * 16;
            unsigned afr[2][4];
#pragma unroll
            for (int mf = 0; mf < 2; mf++)
                ldm4(sptr(a_base + (wm * 32 + mf * 16 + aro) * LDS_H + k0 + aco),
                     afr[mf][0], afr[mf][1], afr[mf][2], afr[mf][3]);
            unsigned bfr[8][2];
#pragma unroll
            for (int j2 = 0; j2 < 4; j2++) {
                unsigned r0, r1, r2, r3;
                ldm4(sptr(b_base + (wn * 64 + j2 * 16 + bro) * LDS_H + k0 + bco), r0, r1, r2, r3);
                bfr[j2 * 2][0] = r0; bfr[j2 * 2][1] = r1;
                bfr[j2 * 2 + 1][0] = r2; bfr[j2 * 2 + 1][1] = r3;
            }
#pragma unroll
            for (int mf = 0; mf < 2; mf++)
#pragma unroll
                for (int j = 0; j < 8; j++) mma16816(acc[mf][j], afr[mf], bfr[j]);
        }
    }

    // ---- epilogue: weighted scatter-add into out (red.global, no return) ----
#pragma unroll
    for (int mf = 0; mf < 2; mf++) {
        int r = wm * 32 + mf * 16 + (lane >> 2);
#pragma unroll
        for (int half_r = 0; half_r < 2; half_r++) {
            int slot = mblk * 64 + r + half_r * 8;
            if (slot < cnt) {
                int   token = g_rowmap[e * CAP + slot];
                float wgt   = g_slotw [e * CAP + slot];
                float* orow = out + (size_t)token * H_DIM;
#pragma unroll
                for (int j = 0; j < 8; j++) {
                    int col = nblk * 128 + wn * 64 + j * 8 + (lane & 3) * 2;
                    float v0 = wgt * acc[mf][j][half_r * 2 + 0];
                    float v1 = wgt * acc[mf][j][half_r * 2 + 1];
                    asm volatile("red.global.add.v2.f32 [%0], {%1, %2};\n"
                                 :: "l"(orow + col), "f"(v0), "f"(v1) : "memory");
                }
            }
        }
    }
}

// ---------------- launch: two-stream overlap via event fork/join ----------------
extern "C" void kernel_launch(void* const* d_in, const int* in_sizes, int n_in,
                              void* d_out, int out_size) {
    const float* hidden = (const float*)d_in[0];
    const float* w1     = (const float*)d_in[1];
    const float* w2     = (const float*)d_in[2];
    const float* tw     = (const float*)d_in[3];
    const int*   ids    = (const int*)d_in[4];
    float*       out    = (float*)d_out;

    static cudaStream_t s2 = nullptr;
    static cudaEvent_t evRoot = nullptr, evW1 = nullptr, evW2 = nullptr;
    if (!s2) {
        cudaStreamCreateWithFlags(&s2, cudaStreamNonBlocking);
        cudaEventCreateWithFlags(&evRoot, cudaEventDisableTiming);
        cudaEventCreateWithFlags(&evW1,   cudaEventDisableTiming);
        cudaEventCreateWithFlags(&evW2,   cudaEventDisableTiming);
        cudaFuncSetAttribute(gemm1_kernel, cudaFuncAttributeMaxDynamicSharedMemorySize, SMEM_GEMM);
        cudaFuncSetAttribute(gemm2_kernel, cudaFuncAttributeMaxDynamicSharedMemorySize, SMEM_GEMM);
    }

    const int N1_BLOCKS = (int)((size_t)E_NUM * 2 * I_DIM * H_DIM / 8 / 256);  // 11264
    const int N2_BLOCKS = (int)((size_t)E_NUM * H_DIM * I_DIM / 8 / 256);      //  5632

    // fork: side stream does weight conversion + output zeroing
    cudaEventRecord(evRoot, 0);
    cudaStreamWaitEvent(s2, evRoot, 0);
    convert_w1_kernel<<<N1_BLOCKS, 256, 0, s2>>>(w1);
    cudaEventRecord(evW1, s2);
    convert_w2_kernel<<<N2_BLOCKS, 256, 0, s2>>>(w2);
    cudaMemsetAsync(d_out, 0, (size_t)out_size * sizeof(float), s2);
    cudaEventRecord(evW2, s2);

    // main stream: routing + token scatter (independent of weight conversion)
    route_kernel<<<1, 256>>>(ids, tw);
    scatter_kernel<<<E_NUM * CAP, 128>>>(hidden);

    cudaStreamWaitEvent(0, evW1, 0);   // gemm1 needs w1h (+ scatter, already ordered)
    gemm1_kernel<<<dim3(I_DIM / 64, CAP / 64, E_NUM), 128, SMEM_GEMM>>>();

    cudaStreamWaitEvent(0, evW2, 0);   // gemm2 needs w2h + zeroed out
    gemm2_kernel<<<dim3(H_DIM / 128, CAP / 64, E_NUM), 128, SMEM_GEMM>>>(out);
}